// round 2
// baseline (speedup 1.0000x reference)
#include <cuda_runtime.h>
#include <math.h>

// Problem dims
#define B_  128
#define R_  1152
#define C_  10
#define O_  16
#define I_  338
#define N_  160               // C_*O_  (n = c*16 + o)
#define BRS (R_*N_)           // 184320 — per-batch stride in u_hat
#define RCHUNK 144            // R_/8 for split-R sv
#define XS_STRIDE 130         // 128 + 2 pad: even (f32x2 aligned), 2-way store conflict only
#define WS_STRIDE 161         // 160 + 1 pad: conflict-free stores

// Scratch (device globals — allocation-free per harness rules)
__device__ float g_uhat[(size_t)B_ * R_ * N_];   // [b][r][n]  ~94.4 MB
__device__ float g_b[R_ * C_];                   // routing logits [r][c]
__device__ float g_c[R_ * C_];                   // softmax coeffs [r][c]
__device__ float g_v[B_ * N_];                   // v [b][n]
__device__ float g_spart[8 * B_ * N_];           // partial s sums [chunk][b][n]

typedef unsigned long long ull;

__device__ __forceinline__ ull pack2(float lo, float hi) {
    ull r;
    asm("mov.b64 %0, {%1, %2};" : "=l"(r) : "f"(lo), "f"(hi));
    return r;
}
__device__ __forceinline__ void unpack2(ull v, float& lo, float& hi) {
    asm("mov.b64 {%0, %1}, %2;" : "=f"(lo), "=f"(hi) : "l"(v));
}
__device__ __forceinline__ void fma2(ull& d, ull a, ull b) {
    asm("fma.rn.f32x2 %0, %1, %2, %3;" : "=l"(d) : "l"(a), "l"(b), "l"(d));
}

// ---------------------------------------------------------------------------
__global__ void zero_b_kernel() {
    int i = blockIdx.x * blockDim.x + threadIdx.x;
    if (i < R_ * C_) g_b[i] = 0.0f;
}

// ---------------------------------------------------------------------------
// u_hat[b][r][n] = sum_i W[r][n][i] * x[b][r][i]
// One block per route r. 256 threads. Per-thread tile: 8 M (as 4 f32x2 pairs)
// x 10 N. Inner product via packed fma.rn.f32x2 (2x fp32 FMA throughput).
#define KC 32
__global__ __launch_bounds__(256) void uhat_kernel(const float* __restrict__ x,
                                                   const float* __restrict__ W) {
    const int r  = blockIdx.x;
    const int t  = threadIdx.x;
    const int tx = t & 15;        // N group: n = in*16 + tx
    const int ty = t >> 4;        // M group: m = ty*8 + 2*p + e

    __shared__ __align__(16) float xs[KC * XS_STRIDE];   // [k][m]
    __shared__ float ws[KC * WS_STRIDE];                 // [k][n]

    const float* xr = x + (size_t)r * I_;
    const float* wr = W + (size_t)r * N_ * I_;

    ull acc[40];                 // [p][in] packed (m_even, m_odd)
#pragma unroll
    for (int i = 0; i < 40; i++) acc[i] = 0ull;

    for (int k0 = 0; k0 < I_; k0 += KC) {
        // x tile: 128 x 32, coalesced gmem (32 consecutive k per m)
        for (int e = t; e < B_ * KC; e += 256) {
            int m = e >> 5, kk = e & 31;
            int k = k0 + kk;
            xs[kk * XS_STRIDE + m] = (k < I_) ? xr[(size_t)m * (R_ * I_) + k] : 0.0f;
        }
        // W tile: 160 x 32
        for (int e = t; e < N_ * KC; e += 256) {
            int n = e >> 5, kk = e & 31;
            int k = k0 + kk;
            ws[kk * WS_STRIDE + n] = (k < I_) ? wr[n * I_ + k] : 0.0f;
        }
        __syncthreads();

#pragma unroll 4
        for (int kk = 0; kk < KC; kk++) {
            const float* xrow = xs + kk * XS_STRIDE;
            const float* wrow = ws + kk * WS_STRIDE;
            ull a[4];
#pragma unroll
            for (int p = 0; p < 4; p++)
                a[p] = *reinterpret_cast<const ull*>(xrow + ty * 8 + 2 * p);
            ull bb[10];
#pragma unroll
            for (int in = 0; in < 10; in++) {
                float w = wrow[in * 16 + tx];
                bb[in] = pack2(w, w);
            }
#pragma unroll
            for (int p = 0; p < 4; p++)
#pragma unroll
                for (int in = 0; in < 10; in++)
                    fma2(acc[p * 10 + in], a[p], bb[in]);
        }
        __syncthreads();
    }

    float* ur = g_uhat + (size_t)r * N_;
#pragma unroll
    for (int p = 0; p < 4; p++) {
        int m0 = ty * 8 + 2 * p;
#pragma unroll
        for (int in = 0; in < 10; in++) {
            float lo, hi;
            unpack2(acc[p * 10 + in], lo, hi);
            ur[(size_t)m0 * BRS + in * 16 + tx]       = lo;
            ur[(size_t)(m0 + 1) * BRS + in * 16 + tx] = hi;
        }
    }
}

// ---------------------------------------------------------------------------
// c[:,c] = softmax over routes (axis=0) of g_b. One block per capsule c.
__global__ void softmax_kernel() {
    const int c = blockIdx.x;
    const int t = threadIdx.x;
    __shared__ float red[256];

    float mx = -1e30f;
    for (int r = t; r < R_; r += 256) mx = fmaxf(mx, g_b[r * C_ + c]);
    red[t] = mx; __syncthreads();
    for (int s = 128; s; s >>= 1) {
        if (t < s) red[t] = fmaxf(red[t], red[t + s]);
        __syncthreads();
    }
    mx = red[0]; __syncthreads();

    float sum = 0.0f;
    for (int r = t; r < R_; r += 256) sum += expf(g_b[r * C_ + c] - mx);
    red[t] = sum; __syncthreads();
    for (int s = 128; s; s >>= 1) {
        if (t < s) red[t] += red[t + s];
        __syncthreads();
    }
    float inv = 1.0f / red[0];

    for (int r = t; r < R_; r += 256)
        g_c[r * C_ + c] = expf(g_b[r * C_ + c] - mx) * inv;
}

// ---------------------------------------------------------------------------
// Split-R partial sums: spart[chunk][b][n] = sum_{r in chunk} c[r][c]*u_hat[b][r][n]
// grid (128 b, 8 chunks), 160 threads.
__global__ __launch_bounds__(160) void sv1_kernel() {
    const int b  = blockIdx.x;
    const int ch = blockIdx.y;
    const int n  = threadIdx.x;
    const int c  = n >> 4;
    const float* ub = g_uhat + (size_t)b * BRS;
    const int r0 = ch * RCHUNK;

    float acc = 0.0f;
#pragma unroll 8
    for (int r = r0; r < r0 + RCHUNK; r++)
        acc += g_c[r * C_ + c] * ub[r * N_ + n];

    g_spart[(ch * B_ + b) * N_ + n] = acc;
}

// Reduce partials + squash. grid 128, 160 threads.
__global__ __launch_bounds__(160) void sv2_kernel(int write_out, float* __restrict__ out) {
    const int b = blockIdx.x;
    const int n = threadIdx.x;
    float s = 0.0f;
#pragma unroll
    for (int q = 0; q < 8; q++) s += g_spart[(q * B_ + b) * N_ + n];
    float v = s * fabsf(s) / (1.0f + s * s);     // squash
    g_v[b * N_ + n] = v;
    if (write_out) out[b * N_ + n] = v;
}

// ---------------------------------------------------------------------------
// b[r][c] += (1/B) * sum_b sum_o u_hat[b][r][c][o] * v[b][c][o]
// One block per route r, 640 threads = 4 parallel b-slices x 160 n.
__global__ __launch_bounds__(640) void agree_kernel() {
    const int r = blockIdx.x;
    const int t = threadIdx.x;
    const int q = t / 160;          // b-slice 0..3
    const int n = t - q * 160;
    const float* up = g_uhat + (size_t)r * N_ + n;

    float acc = 0.0f;
#pragma unroll 4
    for (int b = q; b < B_; b += 4)
        acc += up[(size_t)b * BRS] * g_v[b * N_ + n];

    __shared__ float red[640];
    red[t] = acc;
    __syncthreads();
    if (t < 160) {
        float a = red[t] + red[t + 160] + red[t + 320] + red[t + 480];
#pragma unroll
        for (int off = 8; off; off >>= 1)
            a += __shfl_down_sync(0xffffffffu, a, off, 16);
        if ((t & 15) == 0) g_b[r * C_ + (t >> 4)] += a * (1.0f / 128.0f);
    }
}

// ---------------------------------------------------------------------------
extern "C" void kernel_launch(void* const* d_in, const int* in_sizes, int n_in,
                              void* d_out, int out_size) {
    const float* x = (const float*)d_in[0];
    const float* W = (const float*)d_in[1];
    if (n_in >= 2 && in_sizes[0] == R_ * C_ * O_ * I_) {  // defensive order detect
        W = (const float*)d_in[0];
        x = (const float*)d_in[1];
    }
    float* out = (float*)d_out;

    zero_b_kernel<<<(R_ * C_ + 255) / 256, 256>>>();
    uhat_kernel<<<R_, 256>>>(x, W);
    for (int it = 0; it < 3; it++) {
        softmax_kernel<<<C_, 256>>>();
        sv1_kernel<<<dim3(B_, 8), 160>>>();
        sv2_kernel<<<B_, 160>>>(it == 2 ? 1 : 0, out);
        if (it < 2) agree_kernel<<<R_, 640>>>();
    }
}

// round 3
// speedup vs baseline: 1.2737x; 1.2737x over previous
#include <cuda_runtime.h>
#include <math.h>

// Problem dims
#define B_  128
#define R_  1152
#define C_  10
#define O_  16
#define I_  338
#define N_  160               // C_*O_  (n = c*16 + o)
#define BRS (R_*N_)           // 184320 — per-batch stride in u_hat
#define NCHUNK 16
#define RCHUNK (R_/NCHUNK)    // 72

// Scratch (device globals — allocation-free per harness rules)
__device__ float g_uhat[(size_t)B_ * R_ * N_];   // [b][r][n]  ~94.4 MB
__device__ float g_b[R_ * C_];                   // routing logits [r][c]
__device__ float g_c[R_ * C_];                   // softmax coeffs [r][c]
__device__ float g_v[B_ * N_];                   // v [b][n]
__device__ float g_spart[NCHUNK * B_ * N_];      // partial s sums [chunk][b][n]

// ---------------------------------------------------------------------------
__global__ void zero_b_kernel() {
    int i = blockIdx.x * blockDim.x + threadIdx.x;
    if (i < R_ * C_) g_b[i] = 0.0f;
}

// ---------------------------------------------------------------------------
// u_hat[b][r][n] = sum_i W[r][n][i] * x[b][r][i]
// One block per route r. 256 threads, 8x10 register tile per thread
// (M=128 batch, N=160), K chunked by 32 into padded smem. (Round-1 verified
// version: ~490us, ~90% of fp32 FFMA roofline.)
#define KC 32
__global__ __launch_bounds__(256) void uhat_kernel(const float* __restrict__ x,
                                                   const float* __restrict__ W) {
    const int r  = blockIdx.x;
    const int t  = threadIdx.x;
    const int tx = t & 15;        // N group
    const int ty = t >> 4;        // M group

    __shared__ float xs[KC][B_ + 1];   // [k][m], pad -> conflict-free
    __shared__ float ws[KC][N_ + 1];   // [k][n]

    const float* xr = x + (size_t)r * I_;
    const float* wr = W + (size_t)r * N_ * I_;

    float acc[8][10];
#pragma unroll
    for (int im = 0; im < 8; im++)
#pragma unroll
        for (int in = 0; in < 10; in++) acc[im][in] = 0.0f;

    for (int k0 = 0; k0 < I_; k0 += KC) {
        for (int e = t; e < B_ * KC; e += 256) {
            int m = e >> 5, kk = e & 31;
            int k = k0 + kk;
            xs[kk][m] = (k < I_) ? xr[(size_t)m * (R_ * I_) + k] : 0.0f;
        }
        for (int e = t; e < N_ * KC; e += 256) {
            int n = e >> 5, kk = e & 31;
            int k = k0 + kk;
            ws[kk][n] = (k < I_) ? wr[n * I_ + k] : 0.0f;
        }
        __syncthreads();

#pragma unroll 4
        for (int kk = 0; kk < KC; kk++) {
            float a[8], bb[10];
#pragma unroll
            for (int im = 0; im < 8; im++) a[im] = xs[kk][im * 16 + ty];
#pragma unroll
            for (int in = 0; in < 10; in++) bb[in] = ws[kk][in * 16 + tx];
#pragma unroll
            for (int im = 0; im < 8; im++)
#pragma unroll
                for (int in = 0; in < 10; in++)
                    acc[im][in] = fmaf(a[im], bb[in], acc[im][in]);
        }
        __syncthreads();
    }

    float* ur = g_uhat + (size_t)r * N_;
#pragma unroll
    for (int im = 0; im < 8; im++) {
        int m = im * 16 + ty;
#pragma unroll
        for (int in = 0; in < 10; in++)
            ur[(size_t)m * BRS + in * 16 + tx] = acc[im][in];
    }
}

// ---------------------------------------------------------------------------
// c[:,c] = softmax over routes (axis=0) of g_b. One block per capsule c.
__global__ void softmax_kernel() {
    const int c = blockIdx.x;
    const int t = threadIdx.x;
    __shared__ float red[256];

    float mx = -1e30f;
    for (int r = t; r < R_; r += 256) mx = fmaxf(mx, g_b[r * C_ + c]);
    red[t] = mx; __syncthreads();
    for (int s = 128; s; s >>= 1) {
        if (t < s) red[t] = fmaxf(red[t], red[t + s]);
        __syncthreads();
    }
    mx = red[0]; __syncthreads();

    float sum = 0.0f;
    for (int r = t; r < R_; r += 256) sum += expf(g_b[r * C_ + c] - mx);
    red[t] = sum; __syncthreads();
    for (int s = 128; s; s >>= 1) {
        if (t < s) red[t] += red[t + s];
        __syncthreads();
    }
    float inv = 1.0f / red[0];

    for (int r = t; r < R_; r += 256)
        g_c[r * C_ + c] = expf(g_b[r * C_ + c] - mx) * inv;
}

// ---------------------------------------------------------------------------
// Split-R partial sums: spart[chunk][b][n] = sum_{r in chunk} c[r][c]*u_hat[b][r][n]
// grid (128 b, 16 chunks), 160 threads.
__global__ __launch_bounds__(160) void sv1_kernel() {
    const int b  = blockIdx.x;
    const int ch = blockIdx.y;
    const int n  = threadIdx.x;
    const int c  = n >> 4;
    const float* ub = g_uhat + (size_t)b * BRS;
    const int r0 = ch * RCHUNK;

    float a0 = 0.0f, a1 = 0.0f;
#pragma unroll 4
    for (int r = r0; r < r0 + RCHUNK; r += 2) {
        a0 += g_c[r * C_ + c]       * ub[r * N_ + n];
        a1 += g_c[(r + 1) * C_ + c] * ub[(r + 1) * N_ + n];
    }
    g_spart[(ch * B_ + b) * N_ + n] = a0 + a1;
}

// Reduce partials + squash. grid 128, 160 threads.
__global__ __launch_bounds__(160) void sv2_kernel(int write_out, float* __restrict__ out) {
    const int b = blockIdx.x;
    const int n = threadIdx.x;
    float s = 0.0f;
#pragma unroll
    for (int q = 0; q < NCHUNK; q++) s += g_spart[(q * B_ + b) * N_ + n];
    float v = s * fabsf(s) / (1.0f + s * s);     // squash
    g_v[b * N_ + n] = v;
    if (write_out) out[b * N_ + n] = v;
}

// ---------------------------------------------------------------------------
// b[r][c] += (1/B) * sum_b sum_o u_hat[b][r][c][o] * v[b][c][o]
// One block per route r, 640 threads = 4 parallel b-slices x 160 n.
__global__ __launch_bounds__(640) void agree_kernel() {
    const int r = blockIdx.x;
    const int t = threadIdx.x;
    const int q = t / 160;          // b-slice 0..3
    const int n = t - q * 160;
    const float* up = g_uhat + (size_t)r * N_ + n;

    float acc = 0.0f;
#pragma unroll 4
    for (int b = q; b < B_; b += 4)
        acc += up[(size_t)b * BRS] * g_v[b * N_ + n];

    __shared__ float red[640];
    red[t] = acc;
    __syncthreads();
    if (t < 160) {
        float a = red[t] + red[t + 160] + red[t + 320] + red[t + 480];
#pragma unroll
        for (int off = 8; off; off >>= 1)
            a += __shfl_down_sync(0xffffffffu, a, off, 16);
        if ((t & 15) == 0) g_b[r * C_ + (t >> 4)] += a * (1.0f / 128.0f);
    }
}

// ---------------------------------------------------------------------------
extern "C" void kernel_launch(void* const* d_in, const int* in_sizes, int n_in,
                              void* d_out, int out_size) {
    const float* x = (const float*)d_in[0];
    const float* W = (const float*)d_in[1];
    if (n_in >= 2 && in_sizes[0] == R_ * C_ * O_ * I_) {  // defensive order detect
        W = (const float*)d_in[0];
        x = (const float*)d_in[1];
    }
    float* out = (float*)d_out;

    zero_b_kernel<<<(R_ * C_ + 255) / 256, 256>>>();
    uhat_kernel<<<R_, 256>>>(x, W);
    for (int it = 0; it < 3; it++) {
        softmax_kernel<<<C_, 256>>>();
        sv1_kernel<<<dim3(B_, NCHUNK), 160>>>();
        sv2_kernel<<<B_, 160>>>(it == 2 ? 1 : 0, out);
        if (it < 2) agree_kernel<<<R_, 640>>>();
    }
}

// round 4
// speedup vs baseline: 1.7324x; 1.3601x over previous
#include <cuda_runtime.h>
#include <cuda_bf16.h>
#include <math.h>

// Problem dims
#define B_  128
#define R_  1152
#define C_  10
#define O_  16
#define I_  338
#define N_  160               // C_*O_  (n = c*16 + o)
#define BRS (R_*N_)           // 184320 — per-batch stride in u_hat
#define NCHUNK 8
#define RCHUNK (R_/NCHUNK)    // 144

#define KC 32                 // k-tile per stage
#define AST 40                // smem row stride in bf16 (32 + 8 pad -> conflict-free ldmatrix)
#define NSTAGES 11            // ceil(338/32)

// Scratch (device globals — allocation-free per harness rules)
__device__ float g_uhat[(size_t)B_ * R_ * N_];   // [b][r][n]  ~94.4 MB
__device__ float g_b[R_ * C_];
__device__ float g_c[R_ * C_];
__device__ float g_v[B_ * N_];
__device__ float g_spart[NCHUNK * B_ * N_];

// ---------------------------------------------------------------------------
__device__ __forceinline__ unsigned sptr(const void* p) {
    return (unsigned)__cvta_generic_to_shared(p);
}
__device__ __forceinline__ void ldsm4(unsigned* d, unsigned a) {
    asm volatile("ldmatrix.sync.aligned.m8n8.x4.shared.b16 {%0,%1,%2,%3}, [%4];"
                 : "=r"(d[0]), "=r"(d[1]), "=r"(d[2]), "=r"(d[3]) : "r"(a));
}
__device__ __forceinline__ void ldsm2(unsigned* d, unsigned a) {
    asm volatile("ldmatrix.sync.aligned.m8n8.x2.shared.b16 {%0,%1}, [%2];"
                 : "=r"(d[0]), "=r"(d[1]) : "r"(a));
}
__device__ __forceinline__ void mma16816(float* c, const unsigned* a, const unsigned* b) {
    asm volatile(
        "mma.sync.aligned.m16n8k16.row.col.f32.bf16.bf16.f32 "
        "{%0,%1,%2,%3}, {%4,%5,%6,%7}, {%8,%9}, {%0,%1,%2,%3};"
        : "+f"(c[0]), "+f"(c[1]), "+f"(c[2]), "+f"(c[3])
        : "r"(a[0]), "r"(a[1]), "r"(a[2]), "r"(a[3]), "r"(b[0]), "r"(b[1]));
}

// ---------------------------------------------------------------------------
__global__ void zero_b_kernel() {
    int i = blockIdx.x * blockDim.x + threadIdx.x;
    if (i < R_ * C_) g_b[i] = 0.0f;
}

// ---------------------------------------------------------------------------
// u_hat[b][r][n] = sum_i W[r][n][i] * x[b][r][i], tensor cores via bf16 split:
// x ~= xh + xl, W ~= wh + wl;  acc += xh*wh + xh*wl + xl*wh (fp32 accum).
// One block per route r. 256 threads = 8 warps; warp (wm, wn) owns
// m-tiles {wm*2, wm*2+1} (16 rows each) x n-tiles {wn*10 .. wn*10+9} (8 cols).
__global__ __launch_bounds__(256) void uhat_kernel(const float* __restrict__ x,
                                                   const float* __restrict__ W) {
    const int r    = blockIdx.x;
    const int t    = threadIdx.x;
    const int warp = t >> 5;
    const int lane = t & 31;
    const int wm   = warp >> 1;   // 0..3
    const int wn   = warp & 1;    // 0..1

    __shared__ __nv_bfloat16 a_hi[128 * AST], a_lo[128 * AST];   // x tile [m][kk]
    __shared__ __nv_bfloat16 b_hi[160 * AST], b_lo[160 * AST];   // W tile [n][kk]

    const float* xr = x + (size_t)r * I_;
    const float* wr = W + (size_t)r * N_ * I_;

    float acc[2][10][4];
#pragma unroll
    for (int mi = 0; mi < 2; mi++)
#pragma unroll
        for (int ni = 0; ni < 10; ni++)
#pragma unroll
            for (int q = 0; q < 4; q++) acc[mi][ni][q] = 0.0f;

    // ldmatrix lane address components
    const int a_row_in = lane & 15;          // row within 16-row m-tile
    const int a_kgrp   = (lane >> 4) * 8;    // 0 or 8
    const int b_row_in = lane & 7;           // row within 8-row n-tile
    const int b_kgrp   = ((lane >> 3) & 1) * 8;

    for (int s = 0; s < NSTAGES; s++) {
        const int k0 = s * KC;
        // convert x tile (128 x 32) f32 -> bf16 hi/lo
        for (int e = t; e < 128 * KC; e += 256) {
            int m = e >> 5, kk = e & 31;
            int k = k0 + kk;
            float f = (k < I_) ? xr[(size_t)m * ((size_t)R_ * I_) + k] : 0.0f;
            __nv_bfloat16 h = __float2bfloat16(f);
            a_hi[m * AST + kk] = h;
            a_lo[m * AST + kk] = __float2bfloat16(f - __bfloat162float(h));
        }
        // convert W tile (160 x 32)
        for (int e = t; e < 160 * KC; e += 256) {
            int n = e >> 5, kk = e & 31;
            int k = k0 + kk;
            float f = (k < I_) ? wr[(size_t)n * I_ + k] : 0.0f;
            __nv_bfloat16 h = __float2bfloat16(f);
            b_hi[n * AST + kk] = h;
            b_lo[n * AST + kk] = __float2bfloat16(f - __bfloat162float(h));
        }
        __syncthreads();

#pragma unroll
        for (int h = 0; h < 2; h++) {          // two k16 per stage
            const int kk0 = h * 16;
            unsigned ah[2][4], al[2][4];
#pragma unroll
            for (int mi = 0; mi < 2; mi++) {
                int row = (wm * 2 + mi) * 16 + a_row_in;
                int col = kk0 + a_kgrp;
                ldsm4(ah[mi], sptr(&a_hi[row * AST + col]));
                ldsm4(al[mi], sptr(&a_lo[row * AST + col]));
            }
#pragma unroll
            for (int ni = 0; ni < 10; ni++) {
                int brow = (wn * 10 + ni) * 8 + b_row_in;
                int bcol = kk0 + b_kgrp;
                unsigned bh[2], bl[2];
                ldsm2(bh, sptr(&b_hi[brow * AST + bcol]));
                ldsm2(bl, sptr(&b_lo[brow * AST + bcol]));
#pragma unroll
                for (int mi = 0; mi < 2; mi++) {
                    mma16816(acc[mi][ni], ah[mi], bh);
                    mma16816(acc[mi][ni], ah[mi], bl);
                    mma16816(acc[mi][ni], al[mi], bh);
                }
            }
        }
        __syncthreads();
    }

    // epilogue: c0/c1 at (row=t/4, col=(t%4)*2, +1); c2/c3 at row+8
    float* ur = g_uhat + (size_t)r * N_;
    const int crow = lane >> 2;
    const int ccol = (lane & 3) * 2;
#pragma unroll
    for (int mi = 0; mi < 2; mi++) {
        int m0 = (wm * 2 + mi) * 16 + crow;
#pragma unroll
        for (int ni = 0; ni < 10; ni++) {
            int n0 = (wn * 10 + ni) * 8 + ccol;
            float2 v0 = make_float2(acc[mi][ni][0], acc[mi][ni][1]);
            float2 v1 = make_float2(acc[mi][ni][2], acc[mi][ni][3]);
            *reinterpret_cast<float2*>(&ur[(size_t)m0 * BRS + n0])       = v0;
            *reinterpret_cast<float2*>(&ur[(size_t)(m0 + 8) * BRS + n0]) = v1;
        }
    }
}

// ---------------------------------------------------------------------------
__global__ void softmax_kernel() {
    const int c = blockIdx.x;
    const int t = threadIdx.x;
    __shared__ float red[256];

    float mx = -1e30f;
    for (int r = t; r < R_; r += 256) mx = fmaxf(mx, g_b[r * C_ + c]);
    red[t] = mx; __syncthreads();
    for (int s = 128; s; s >>= 1) {
        if (t < s) red[t] = fmaxf(red[t], red[t + s]);
        __syncthreads();
    }
    mx = red[0]; __syncthreads();

    float sum = 0.0f;
    for (int r = t; r < R_; r += 256) sum += expf(g_b[r * C_ + c] - mx);
    red[t] = sum; __syncthreads();
    for (int s = 128; s; s >>= 1) {
        if (t < s) red[t] += red[t + s];
        __syncthreads();
    }
    float inv = 1.0f / red[0];

    for (int r = t; r < R_; r += 256)
        g_c[r * C_ + c] = expf(g_b[r * C_ + c] - mx) * inv;
}

// ---------------------------------------------------------------------------
// spart[ch][b][n] = sum_{r in chunk} c[r][c]*u_hat[b][r][n]. grid (128, 8), 160 thr.
__global__ __launch_bounds__(160) void sv1_kernel() {
    const int b  = blockIdx.x;
    const int ch = blockIdx.y;
    const int n  = threadIdx.x;
    const int c  = n >> 4;
    const float* ub = g_uhat + (size_t)b * BRS;
    const int r0 = ch * RCHUNK;

    float a0 = 0.0f, a1 = 0.0f;
#pragma unroll 4
    for (int r = r0; r < r0 + RCHUNK; r += 2) {
        a0 += g_c[r * C_ + c]       * ub[r * N_ + n];
        a1 += g_c[(r + 1) * C_ + c] * ub[(r + 1) * N_ + n];
    }
    g_spart[(ch * B_ + b) * N_ + n] = a0 + a1;
}

// Reduce partials + squash. grid 128, 160 threads.
__global__ __launch_bounds__(160) void sv2_kernel(int write_out, float* __restrict__ out) {
    const int b = blockIdx.x;
    const int n = threadIdx.x;
    float s = 0.0f;
#pragma unroll
    for (int q = 0; q < NCHUNK; q++) s += g_spart[(q * B_ + b) * N_ + n];
    float v = s * fabsf(s) / (1.0f + s * s);     // squash
    g_v[b * N_ + n] = v;
    if (write_out) out[b * N_ + n] = v;
}

// ---------------------------------------------------------------------------
// b[r][c] += (1/B) * sum_b sum_o u_hat[b][r][c][o] * v[b][c][o]. 640 thr/route.
__global__ __launch_bounds__(640) void agree_kernel() {
    const int r = blockIdx.x;
    const int t = threadIdx.x;
    const int q = t / 160;
    const int n = t - q * 160;
    const float* up = g_uhat + (size_t)r * N_ + n;

    float acc = 0.0f;
#pragma unroll 4
    for (int b = q; b < B_; b += 4)
        acc += up[(size_t)b * BRS] * g_v[b * N_ + n];

    __shared__ float red[640];
    red[t] = acc;
    __syncthreads();
    if (t < 160) {
        float a = red[t] + red[t + 160] + red[t + 320] + red[t + 480];
#pragma unroll
        for (int off = 8; off; off >>= 1)
            a += __shfl_down_sync(0xffffffffu, a, off, 16);
        if ((t & 15) == 0) g_b[r * C_ + (t >> 4)] += a * (1.0f / 128.0f);
    }
}

// ---------------------------------------------------------------------------
extern "C" void kernel_launch(void* const* d_in, const int* in_sizes, int n_in,
                              void* d_out, int out_size) {
    const float* x = (const float*)d_in[0];
    const float* W = (const float*)d_in[1];
    if (n_in >= 2 && in_sizes[0] == R_ * C_ * O_ * I_) {  // defensive order detect
        W = (const float*)d_in[0];
        x = (const float*)d_in[1];
    }
    float* out = (float*)d_out;

    zero_b_kernel<<<(R_ * C_ + 255) / 256, 256>>>();
    uhat_kernel<<<R_, 256>>>(x, W);
    for (int it = 0; it < 3; it++) {
        softmax_kernel<<<C_, 256>>>();
        sv1_kernel<<<dim3(B_, NCHUNK), 160>>>();
        sv2_kernel<<<B_, 160>>>(it == 2 ? 1 : 0, out);
        if (it < 2) agree_kernel<<<R_, 640>>>();
    }
}

// round 6
// speedup vs baseline: 2.1064x; 1.2158x over previous
#include <cuda_runtime.h>
#include <cuda_bf16.h>
#include <math.h>

// Problem dims
#define B_  128
#define R_  1152
#define C_  10
#define O_  16
#define I_  338
#define N_  160               // C_*O_  (n = c*16 + o)
#define BRS (R_*N_)
#define NCHUNK 8
#define RCHUNK (R_/NCHUNK)    // 144

#define KC 32                 // k-tile per stage
#define AST 40                // smem row stride in bf16 (80B = 5*16B, ldmatrix-aligned, conflict-free)
#define NSTAGES 11            // ceil(338/32)
#define NH 80                 // N per block (half)

// Scratch
__device__ float g_uhat[(size_t)B_ * R_ * N_];   // [b][r][n]
__device__ float g_b[R_ * C_];
__device__ float g_c[R_ * C_];
__device__ float g_v[B_ * N_];
__device__ float g_spart[NCHUNK * B_ * N_];

// ---------------------------------------------------------------------------
__device__ __forceinline__ unsigned sptr(const void* p) {
    return (unsigned)__cvta_generic_to_shared(p);
}
__device__ __forceinline__ void ldsm4(unsigned* d, unsigned a) {
    asm volatile("ldmatrix.sync.aligned.m8n8.x4.shared.b16 {%0,%1,%2,%3}, [%4];"
                 : "=r"(d[0]), "=r"(d[1]), "=r"(d[2]), "=r"(d[3]) : "r"(a));
}
__device__ __forceinline__ void ldsm2(unsigned* d, unsigned a) {
    asm volatile("ldmatrix.sync.aligned.m8n8.x2.shared.b16 {%0,%1}, [%2];"
                 : "=r"(d[0]), "=r"(d[1]) : "r"(a));
}
__device__ __forceinline__ void mma16816(float* c, const unsigned* a, const unsigned* b) {
    asm volatile(
        "mma.sync.aligned.m16n8k16.row.col.f32.bf16.bf16.f32 "
        "{%0,%1,%2,%3}, {%4,%5,%6,%7}, {%8,%9}, {%0,%1,%2,%3};"
        : "+f"(c[0]), "+f"(c[1]), "+f"(c[2]), "+f"(c[3])
        : "r"(a[0]), "r"(a[1]), "r"(a[2]), "r"(a[3]), "r"(b[0]), "r"(b[1]));
}

// ---------------------------------------------------------------------------
__global__ void init_kernel() {
    int i = blockIdx.x * blockDim.x + threadIdx.x;
    if (i < R_ * C_) {
        g_b[i] = 0.0f;
        g_c[i] = 1.0f / (float)R_;   // softmax of all-zero logits over routes
    }
}

// ---------------------------------------------------------------------------
// u_hat[b][r][n] = sum_i W[r][n][i]*x[b][r][i] — bf16 hi/lo split on HMMA.
// grid (R_, 2): route r, N-half. Block 256 thr = 8 warps.
// Warp (wm, wn): m-tiles {wm*2, wm*2+1} (16 rows), n-tiles {wn*5..wn*5+4} (8 cols).
// acc[2][5][4] = 40 regs -> 2 CTAs/SM (4 warps/SMSP hides HMMA latency).
__global__ __launch_bounds__(256, 2) void uhat_kernel(const float* __restrict__ x,
                                                      const float* __restrict__ W) {
    const int r     = blockIdx.x;
    const int nhalf = blockIdx.y;
    const int t     = threadIdx.x;
    const int warp  = t >> 5;
    const int lane  = t & 31;
    const int wm    = warp >> 1;   // 0..3
    const int wn    = warp & 1;    // 0..1

    __shared__ __nv_bfloat16 a_hi[128 * AST], a_lo[128 * AST];  // x tile [m][kk]
    __shared__ __nv_bfloat16 b_hi[NH * AST],  b_lo[NH * AST];   // W tile [n][kk]

    const float* xr = x + (size_t)r * I_;
    const float* wr = W + (size_t)r * N_ * I_ + (size_t)nhalf * NH * I_;

    float acc[2][5][4];
#pragma unroll
    for (int mi = 0; mi < 2; mi++)
#pragma unroll
        for (int ni = 0; ni < 5; ni++)
#pragma unroll
            for (int q = 0; q < 4; q++) acc[mi][ni][q] = 0.0f;

    // ldmatrix lane addressing
    const int a_row_in = lane & 15;            // row within 16-row m-tile
    const int a_kgrp   = (lane >> 4) * 8;      // 0 / 8
    const int b_row_in = lane & 7;
    const int b_kgrp   = ((lane >> 3) & 1) * 8;
    const int b_tsel   = lane >> 4;            // tile pair selector for ldsm4

    for (int s = 0; s < NSTAGES; s++) {
        const int k0 = s * KC;
        // convert x tile: 128 x 32 (16 f32-pairs per row)
        for (int e = t; e < 128 * 16; e += 256) {
            int m = e >> 4, p = e & 15;
            int k = p * 2, kg = k0 + k;
            float2 f = make_float2(0.0f, 0.0f);
            if (kg < I_) f = *reinterpret_cast<const float2*>(
                                 xr + (size_t)m * ((size_t)R_ * I_) + kg);
            __nv_bfloat16 h0 = __float2bfloat16(f.x), h1 = __float2bfloat16(f.y);
            __nv_bfloat16 l0 = __float2bfloat16(f.x - __bfloat162float(h0));
            __nv_bfloat16 l1 = __float2bfloat16(f.y - __bfloat162float(h1));
            *reinterpret_cast<__nv_bfloat162*>(&a_hi[m * AST + k]) = __halves2bfloat162(h0, h1);
            *reinterpret_cast<__nv_bfloat162*>(&a_lo[m * AST + k]) = __halves2bfloat162(l0, l1);
        }
        // convert W tile: 80 x 32
        for (int e = t; e < NH * 16; e += 256) {
            int n = e >> 4, p = e & 15;
            int k = p * 2, kg = k0 + k;
            float2 f = make_float2(0.0f, 0.0f);
            if (kg < I_) f = *reinterpret_cast<const float2*>(wr + (size_t)n * I_ + kg);
            __nv_bfloat16 h0 = __float2bfloat16(f.x), h1 = __float2bfloat16(f.y);
            __nv_bfloat16 l0 = __float2bfloat16(f.x - __bfloat162float(h0));
            __nv_bfloat16 l1 = __float2bfloat16(f.y - __bfloat162float(h1));
            *reinterpret_cast<__nv_bfloat162*>(&b_hi[n * AST + k]) = __halves2bfloat162(h0, h1);
            *reinterpret_cast<__nv_bfloat162*>(&b_lo[n * AST + k]) = __halves2bfloat162(l0, l1);
        }
        __syncthreads();

#pragma unroll
        for (int h = 0; h < 2; h++) {
            const int kk0 = h * 16;
            // A fragments: 2 m-tiles, hi+lo
            unsigned ah[2][4], al[2][4];
#pragma unroll
            for (int mi = 0; mi < 2; mi++) {
                int row = (wm * 2 + mi) * 16 + a_row_in;
                int col = kk0 + a_kgrp;
                ldsm4(ah[mi], sptr(&a_hi[row * AST + col]));
                ldsm4(al[mi], sptr(&a_lo[row * AST + col]));
            }
            // B fragments: 5 n-tiles, hi+lo. Pairs via ldsm4, last via ldsm2.
            unsigned bh[5][2], bl[5][2];
#pragma unroll
            for (int q = 0; q < 2; q++) {
                int row = (wn * 5 + q * 2 + b_tsel) * 8 + b_row_in;
                int col = kk0 + b_kgrp;
                unsigned d4[4];
                ldsm4(d4, sptr(&b_hi[row * AST + col]));
                bh[q * 2][0] = d4[0]; bh[q * 2][1] = d4[1];
                bh[q * 2 + 1][0] = d4[2]; bh[q * 2 + 1][1] = d4[3];
                ldsm4(d4, sptr(&b_lo[row * AST + col]));
                bl[q * 2][0] = d4[0]; bl[q * 2][1] = d4[1];
                bl[q * 2 + 1][0] = d4[2]; bl[q * 2 + 1][1] = d4[3];
            }
            {
                int row = (wn * 5 + 4) * 8 + b_row_in;
                int col = kk0 + b_kgrp;
                ldsm2(bh[4], sptr(&b_hi[row * AST + col]));
                ldsm2(bl[4], sptr(&b_lo[row * AST + col]));
            }
            // product-major: consecutive MMAs hit distinct accumulators
#pragma unroll
            for (int ni = 0; ni < 5; ni++)
#pragma unroll
                for (int mi = 0; mi < 2; mi++)
                    mma16816(acc[mi][ni], ah[mi], bh[ni]);
#pragma unroll
            for (int ni = 0; ni < 5; ni++)
#pragma unroll
                for (int mi = 0; mi < 2; mi++)
                    mma16816(acc[mi][ni], ah[mi], bl[ni]);
#pragma unroll
            for (int ni = 0; ni < 5; ni++)
#pragma unroll
                for (int mi = 0; mi < 2; mi++)
                    mma16816(acc[mi][ni], al[mi], bh[ni]);
        }
        __syncthreads();
    }

    // epilogue: fragment -> gmem (float2 per row-half)
    float* ur = g_uhat + (size_t)r * N_ + (size_t)nhalf * NH;
    const int crow = lane >> 2;
    const int ccol = (lane & 3) * 2;
#pragma unroll
    for (int mi = 0; mi < 2; mi++) {
        int m0 = (wm * 2 + mi) * 16 + crow;
#pragma unroll
        for (int ni = 0; ni < 5; ni++) {
            int n0 = (wn * 5 + ni) * 8 + ccol;
            *reinterpret_cast<float2*>(&ur[(size_t)m0 * BRS + n0]) =
                make_float2(acc[mi][ni][0], acc[mi][ni][1]);
            *reinterpret_cast<float2*>(&ur[(size_t)(m0 + 8) * BRS + n0]) =
                make_float2(acc[mi][ni][2], acc[mi][ni][3]);
        }
    }
}

// ---------------------------------------------------------------------------
__global__ void softmax_kernel() {
    const int c = blockIdx.x;
    const int t = threadIdx.x;
    __shared__ float red[256];

    float mx = -1e30f;
    for (int r = t; r < R_; r += 256) mx = fmaxf(mx, g_b[r * C_ + c]);
    red[t] = mx; __syncthreads();
    for (int s = 128; s; s >>= 1) {
        if (t < s) red[t] = fmaxf(red[t], red[t + s]);
        __syncthreads();
    }
    mx = red[0]; __syncthreads();

    float sum = 0.0f;
    for (int r = t; r < R_; r += 256) sum += expf(g_b[r * C_ + c] - mx);
    red[t] = sum; __syncthreads();
    for (int s = 128; s; s >>= 1) {
        if (t < s) red[t] += red[t + s];
        __syncthreads();
    }
    float inv = 1.0f / red[0];

    for (int r = t; r < R_; r += 256)
        g_c[r * C_ + c] = expf(g_b[r * C_ + c] - mx) * inv;
}

// ---------------------------------------------------------------------------
__global__ __launch_bounds__(160) void sv1_kernel() {
    const int b  = blockIdx.x;
    const int ch = blockIdx.y;
    const int n  = threadIdx.x;
    const int c  = n >> 4;
    const float* ub = g_uhat + (size_t)b * BRS;
    const int r0 = ch * RCHUNK;

    float a0 = 0.0f, a1 = 0.0f;
#pragma unroll 4
    for (int r = r0; r < r0 + RCHUNK; r += 2) {
        a0 += g_c[r * C_ + c]       * ub[r * N_ + n];
        a1 += g_c[(r + 1) * C_ + c] * ub[(r + 1) * N_ + n];
    }
    g_spart[(ch * B_ + b) * N_ + n] = a0 + a1;
}

__global__ __launch_bounds__(160) void sv2_kernel(int write_out, float* __restrict__ out) {
    const int b = blockIdx.x;
    const int n = threadIdx.x;
    float s = 0.0f;
#pragma unroll
    for (int q = 0; q < NCHUNK; q++) s += g_spart[(q * B_ + b) * N_ + n];
    float v = s * fabsf(s) / (1.0f + s * s);
    g_v[b * N_ + n] = v;
    if (write_out) out[b * N_ + n] = v;
}

// ---------------------------------------------------------------------------
__global__ __launch_bounds__(640) void agree_kernel() {
    const int r = blockIdx.x;
    const int t = threadIdx.x;
    const int q = t / 160;
    const int n = t - q * 160;
    const float* up = g_uhat + (size_t)r * N_ + n;

    float acc = 0.0f;
#pragma unroll 4
    for (int b = q; b < B_; b += 4)
        acc += up[(size_t)b * BRS] * g_v[b * N_ + n];

    __shared__ float red[640];
    red[t] = acc;
    __syncthreads();
    if (t < 160) {
        float a = red[t] + red[t + 160] + red[t + 320] + red[t + 480];
#pragma unroll
        for (int off = 8; off; off >>= 1)
            a += __shfl_down_sync(0xffffffffu, a, off, 16);
        if ((t & 15) == 0) g_b[r * C_ + (t >> 4)] += a * (1.0f / 128.0f);
    }
}

// ---------------------------------------------------------------------------
extern "C" void kernel_launch(void* const* d_in, const int* in_sizes, int n_in,
                              void* d_out, int out_size) {
    const float* x = (const float*)d_in[0];
    const float* W = (const float*)d_in[1];
    if (n_in >= 2 && in_sizes[0] == R_ * C_ * O_ * I_) {  // defensive order detect
        W = (const float*)d_in[0];
        x = (const float*)d_in[1];
    }
    float* out = (float*)d_out;

    // 5 idempotent pre-launches so ncu (-s 5 -c 1) captures uhat_kernel.
    for (int i = 0; i < 5; i++)
        init_kernel<<<(R_ * C_ + 255) / 256, 256>>>();
    uhat_kernel<<<dim3(R_, 2), 256>>>(x, W);
    for (int it = 0; it < 3; it++) {
        if (it > 0) softmax_kernel<<<C_, 256>>>();   // iter 0: uniform c from init
        sv1_kernel<<<dim3(B_, NCHUNK), 160>>>();
        sv2_kernel<<<B_, 160>>>(it == 2 ? 1 : 0, out);
        if (it < 2) agree_kernel<<<R_, 640>>>();
    }
}

// round 7
// speedup vs baseline: 3.6449x; 1.7304x over previous
#include <cuda_runtime.h>
#include <cuda_bf16.h>
#include <math.h>

// Problem dims
#define B_  128
#define R_  1152
#define C_  10
#define O_  16
#define I_  338
#define N_  160
#define BRS (R_*N_)
#define NCHUNK 8
#define RCHUNK (R_/NCHUNK)    // 144

#define KC 16                 // k per stage
#define AST 24                // row stride in bf16 (48B; conflict-free ldmatrix)
#define NSTAGES 22            // ceil(338/16)
#define NH 80                 // N per block

// Scratch
__device__ float g_uhat[(size_t)B_ * R_ * N_];
__device__ float g_b[R_ * C_];
__device__ float g_c[R_ * C_];
__device__ float g_v[B_ * N_];
__device__ float g_spart[NCHUNK * B_ * N_];

// ---------------------------------------------------------------------------
__device__ __forceinline__ unsigned sptr(const void* p) {
    return (unsigned)__cvta_generic_to_shared(p);
}
__device__ __forceinline__ void ldsm4(unsigned* d, unsigned a) {
    asm volatile("ldmatrix.sync.aligned.m8n8.x4.shared.b16 {%0,%1,%2,%3}, [%4];"
                 : "=r"(d[0]), "=r"(d[1]), "=r"(d[2]), "=r"(d[3]) : "r"(a));
}
__device__ __forceinline__ void ldsm2(unsigned* d, unsigned a) {
    asm volatile("ldmatrix.sync.aligned.m8n8.x2.shared.b16 {%0,%1}, [%2];"
                 : "=r"(d[0]), "=r"(d[1]) : "r"(a));
}
__device__ __forceinline__ void mma16816(float* c, const unsigned* a, const unsigned* b) {
    asm volatile(
        "mma.sync.aligned.m16n8k16.row.col.f32.bf16.bf16.f32 "
        "{%0,%1,%2,%3}, {%4,%5,%6,%7}, {%8,%9}, {%0,%1,%2,%3};"
        : "+f"(c[0]), "+f"(c[1]), "+f"(c[2]), "+f"(c[3])
        : "r"(a[0]), "r"(a[1]), "r"(a[2]), "r"(a[3]), "r"(b[0]), "r"(b[1]));
}

// ---------------------------------------------------------------------------
__global__ void init_kernel() {
    int i = blockIdx.x * blockDim.x + threadIdx.x;
    if (i < R_ * C_) {
        g_b[i] = 0.0f;
        g_c[i] = 1.0f / (float)R_;   // softmax of zero logits over routes
    }
}

// ---------------------------------------------------------------------------
// u_hat via bf16 hi/lo split HMMA, software-pipelined (double-buffered smem).
// grid (R_, 2). 256 thr = 8 warps. Warp (wm, wn): 2 m-tiles x 5 n-tiles.
__global__ __launch_bounds__(256, 2) void uhat_kernel(const float* __restrict__ x,
                                                      const float* __restrict__ W) {
    const int r     = blockIdx.x;
    const int nhalf = blockIdx.y;
    const int t     = threadIdx.x;
    const int warp  = t >> 5;
    const int lane  = t & 31;
    const int wm    = warp >> 1;
    const int wn    = warp & 1;

    __shared__ __nv_bfloat16 a_hi[2][128 * AST], a_lo[2][128 * AST];
    __shared__ __nv_bfloat16 b_hi[2][NH * AST],  b_lo[2][NH * AST];

    const float* xr = x + (size_t)r * I_;
    const float* wr = W + (size_t)r * N_ * I_ + (size_t)nhalf * NH * I_;

    float acc[2][5][4];
#pragma unroll
    for (int mi = 0; mi < 2; mi++)
#pragma unroll
        for (int ni = 0; ni < 5; ni++)
#pragma unroll
            for (int q = 0; q < 4; q++) acc[mi][ni][q] = 0.0f;

    // per-thread load coordinates (fixed across stages)
    // x: 4 entries, e = t + j*256, m = e>>3, pair p = e&7, k = 2p
    // W: 3 entries (last predicated)
    const int a_row_in = lane & 15;
    const int a_kgrp   = (lane >> 4) * 8;
    const int b_row_in = lane & 7;
    const int b_kgrp   = ((lane >> 3) & 1) * 8;
    const int b_tsel   = lane >> 4;

    float2 xa[4], wb[3];

    // ---- stage-load into regs ----
    auto load_regs = [&](int s) {
        const int k0 = s * KC;
#pragma unroll
        for (int j = 0; j < 4; j++) {
            int e = t + j * 256;
            int m = e >> 3, k = (e & 7) * 2, kg = k0 + k;
            xa[j] = (kg < I_) ? *reinterpret_cast<const float2*>(
                                    xr + (size_t)m * ((size_t)R_ * I_) + kg)
                              : make_float2(0.0f, 0.0f);
        }
#pragma unroll
        for (int j = 0; j < 3; j++) {
            int e = t + j * 256;
            int n = e >> 3, k = (e & 7) * 2, kg = k0 + k;
            wb[j] = (e < NH * 8 && kg < I_)
                        ? *reinterpret_cast<const float2*>(wr + (size_t)n * I_ + kg)
                        : make_float2(0.0f, 0.0f);
        }
    };
    // ---- convert regs -> smem buffer ----
    auto cvt_store = [&](int buf) {
#pragma unroll
        for (int j = 0; j < 4; j++) {
            int e = t + j * 256;
            int m = e >> 3, k = (e & 7) * 2;
            __nv_bfloat16 h0 = __float2bfloat16(xa[j].x), h1 = __float2bfloat16(xa[j].y);
            __nv_bfloat16 l0 = __float2bfloat16(xa[j].x - __bfloat162float(h0));
            __nv_bfloat16 l1 = __float2bfloat16(xa[j].y - __bfloat162float(h1));
            *reinterpret_cast<__nv_bfloat162*>(&a_hi[buf][m * AST + k]) = __halves2bfloat162(h0, h1);
            *reinterpret_cast<__nv_bfloat162*>(&a_lo[buf][m * AST + k]) = __halves2bfloat162(l0, l1);
        }
#pragma unroll
        for (int j = 0; j < 3; j++) {
            int e = t + j * 256;
            if (e < NH * 8) {
                int n = e >> 3, k = (e & 7) * 2;
                __nv_bfloat16 h0 = __float2bfloat16(wb[j].x), h1 = __float2bfloat16(wb[j].y);
                __nv_bfloat16 l0 = __float2bfloat16(wb[j].x - __bfloat162float(h0));
                __nv_bfloat16 l1 = __float2bfloat16(wb[j].y - __bfloat162float(h1));
                *reinterpret_cast<__nv_bfloat162*>(&b_hi[buf][n * AST + k]) = __halves2bfloat162(h0, h1);
                *reinterpret_cast<__nv_bfloat162*>(&b_lo[buf][n * AST + k]) = __halves2bfloat162(l0, l1);
            }
        }
    };

    // prologue
    load_regs(0);
    cvt_store(0);
    __syncthreads();

    for (int s = 0; s < NSTAGES; s++) {
        const int cur = s & 1;
        if (s + 1 < NSTAGES) load_regs(s + 1);   // LDGs overlap the MMAs below

        // ---- MMA on buffer cur ----
        unsigned ah[2][4], al[2][4];
#pragma unroll
        for (int mi = 0; mi < 2; mi++) {
            int row = (wm * 2 + mi) * 16 + a_row_in;
            ldsm4(ah[mi], sptr(&a_hi[cur][row * AST + a_kgrp]));
            ldsm4(al[mi], sptr(&a_lo[cur][row * AST + a_kgrp]));
        }
        unsigned bh[5][2], bl[5][2];
#pragma unroll
        for (int q = 0; q < 2; q++) {
            int row = (wn * 5 + q * 2 + b_tsel) * 8 + b_row_in;
            unsigned d4[4];
            ldsm4(d4, sptr(&b_hi[cur][row * AST + b_kgrp]));
            bh[q * 2][0] = d4[0]; bh[q * 2][1] = d4[1];
            bh[q * 2 + 1][0] = d4[2]; bh[q * 2 + 1][1] = d4[3];
            ldsm4(d4, sptr(&b_lo[cur][row * AST + b_kgrp]));
            bl[q * 2][0] = d4[0]; bl[q * 2][1] = d4[1];
            bl[q * 2 + 1][0] = d4[2]; bl[q * 2 + 1][1] = d4[3];
        }
        {
            int row = (wn * 5 + 4) * 8 + b_row_in;
            ldsm2(bh[4], sptr(&b_hi[cur][row * AST + b_kgrp]));
            ldsm2(bl[4], sptr(&b_lo[cur][row * AST + b_kgrp]));
        }
#pragma unroll
        for (int ni = 0; ni < 5; ni++)
#pragma unroll
            for (int mi = 0; mi < 2; mi++)
                mma16816(acc[mi][ni], ah[mi], bh[ni]);
#pragma unroll
        for (int ni = 0; ni < 5; ni++)
#pragma unroll
            for (int mi = 0; mi < 2; mi++)
                mma16816(acc[mi][ni], ah[mi], bl[ni]);
#pragma unroll
        for (int ni = 0; ni < 5; ni++)
#pragma unroll
            for (int mi = 0; mi < 2; mi++)
                mma16816(acc[mi][ni], al[mi], bh[ni]);

        if (s + 1 < NSTAGES) cvt_store((s + 1) & 1);
        __syncthreads();
    }

    // epilogue: fragments -> gmem
    float* ur = g_uhat + (size_t)r * N_ + (size_t)nhalf * NH;
    const int crow = lane >> 2;
    const int ccol = (lane & 3) * 2;
#pragma unroll
    for (int mi = 0; mi < 2; mi++) {
        int m0 = (wm * 2 + mi) * 16 + crow;
#pragma unroll
        for (int ni = 0; ni < 5; ni++) {
            int n0 = (wn * 5 + ni) * 8 + ccol;
            *reinterpret_cast<float2*>(&ur[(size_t)m0 * BRS + n0]) =
                make_float2(acc[mi][ni][0], acc[mi][ni][1]);
            *reinterpret_cast<float2*>(&ur[(size_t)(m0 + 8) * BRS + n0]) =
                make_float2(acc[mi][ni][2], acc[mi][ni][3]);
        }
    }
}

// ---------------------------------------------------------------------------
__global__ void softmax_kernel() {
    const int c = blockIdx.x;
    const int t = threadIdx.x;
    __shared__ float red[256];

    float mx = -1e30f;
    for (int r = t; r < R_; r += 256) mx = fmaxf(mx, g_b[r * C_ + c]);
    red[t] = mx; __syncthreads();
    for (int s = 128; s; s >>= 1) {
        if (t < s) red[t] = fmaxf(red[t], red[t + s]);
        __syncthreads();
    }
    mx = red[0]; __syncthreads();

    float sum = 0.0f;
    for (int r = t; r < R_; r += 256) sum += expf(g_b[r * C_ + c] - mx);
    red[t] = sum; __syncthreads();
    for (int s = 128; s; s >>= 1) {
        if (t < s) red[t] += red[t + s];
        __syncthreads();
    }
    float inv = 1.0f / red[0];

    for (int r = t; r < R_; r += 256)
        g_c[r * C_ + c] = expf(g_b[r * C_ + c] - mx) * inv;
}

// ---------------------------------------------------------------------------
__global__ __launch_bounds__(160) void sv1_kernel() {
    const int b  = blockIdx.x;
    const int ch = blockIdx.y;
    const int n  = threadIdx.x;
    const int c  = n >> 4;
    const float* ub = g_uhat + (size_t)b * BRS;
    const int r0 = ch * RCHUNK;

    float a0 = 0.0f, a1 = 0.0f;
#pragma unroll 4
    for (int r = r0; r < r0 + RCHUNK; r += 2) {
        a0 += g_c[r * C_ + c]       * ub[r * N_ + n];
        a1 += g_c[(r + 1) * C_ + c] * ub[(r + 1) * N_ + n];
    }
    g_spart[(ch * B_ + b) * N_ + n] = a0 + a1;
}

__global__ __launch_bounds__(160) void sv2_kernel(int write_out, float* __restrict__ out) {
    const int b = blockIdx.x;
    const int n = threadIdx.x;
    float s = 0.0f;
#pragma unroll
    for (int q = 0; q < NCHUNK; q++) s += g_spart[(q * B_ + b) * N_ + n];
    float v = s * fabsf(s) / (1.0f + s * s);
    g_v[b * N_ + n] = v;
    if (write_out) out[b * N_ + n] = v;
}

// ---------------------------------------------------------------------------
__global__ __launch_bounds__(640) void agree_kernel() {
    const int r = blockIdx.x;
    const int t = threadIdx.x;
    const int q = t / 160;
    const int n = t - q * 160;
    const float* up = g_uhat + (size_t)r * N_ + n;

    float acc = 0.0f;
#pragma unroll 4
    for (int b = q; b < B_; b += 4)
        acc += up[(size_t)b * BRS] * g_v[b * N_ + n];

    __shared__ float red[640];
    red[t] = acc;
    __syncthreads();
    if (t < 160) {
        float a = red[t] + red[t + 160] + red[t + 320] + red[t + 480];
#pragma unroll
        for (int off = 8; off; off >>= 1)
            a += __shfl_down_sync(0xffffffffu, a, off, 16);
        if ((t & 15) == 0) g_b[r * C_ + (t >> 4)] += a * (1.0f / 128.0f);
    }
}

// ---------------------------------------------------------------------------
extern "C" void kernel_launch(void* const* d_in, const int* in_sizes, int n_in,
                              void* d_out, int out_size) {
    const float* x = (const float*)d_in[0];
    const float* W = (const float*)d_in[1];
    if (n_in >= 2 && in_sizes[0] == R_ * C_ * O_ * I_) {  // defensive order detect
        W = (const float*)d_in[0];
        x = (const float*)d_in[1];
    }
    float* out = (float*)d_out;

    // Launches 0-2: idempotent init; launch index 3 = uhat (ncu capture slot).
    for (int i = 0; i < 3; i++)
        init_kernel<<<(R_ * C_ + 255) / 256, 256>>>();
    uhat_kernel<<<dim3(R_, 2), 256>>>(x, W);
    for (int it = 0; it < 3; it++) {
        if (it > 0) softmax_kernel<<<C_, 256>>>();   // iter 0: uniform c from init
        sv1_kernel<<<dim3(B_, NCHUNK), 160>>>();
        sv2_kernel<<<B_, 160>>>(it == 2 ? 1 : 0, out);
        if (it < 2) agree_kernel<<<R_, 640>>>();
    }
}